// round 8
// baseline (speedup 1.0000x reference)
#include <cuda_runtime.h>
#include <cuda_fp16.h>
#include <math_constants.h>

// Problem constants (fixed by the dataset)
constexpr int NN = 100000;   // nodes
constexpr int EE = 1600000;  // edges
constexpr int DD = 128;      // model dim
constexpr int HH = 8;        // heads
// DH = 16, M = 3

// ---------------- scratch (static device globals; no allocation) -------------
__device__ float  g_Q[NN * DD];
__device__ __half g_KVh[NN * 256];    // per node: K[128 halfs] then V[128 halfs]
__device__ int    g_deg[NN];
__device__ int    g_rowptr[NN + 1];
__device__ int    g_cursor[NN];
__device__ int2   g_edge[EE];         // (eid, src) packed
__device__ float  g_scores[(size_t)EE * HH];  // raw scores in CSR order
__device__ int    g_bsum[128];

// ---------------- TF32 helpers ------------------------------------------------
__device__ __forceinline__ float to_tf32(float a) {
    float r; asm("cvt.rna.tf32.f32 %0, %1;" : "=f"(r) : "f"(a)); return r;
}

__device__ __forceinline__ void mma_tf32(float c[4], const unsigned a[4],
                                         const unsigned b[2]) {
    asm volatile(
        "mma.sync.aligned.m16n8k8.row.col.f32.tf32.tf32.f32 "
        "{%0,%1,%2,%3}, {%4,%5,%6,%7}, {%8,%9}, {%0,%1,%2,%3};"
        : "+f"(c[0]), "+f"(c[1]), "+f"(c[2]), "+f"(c[3])
        : "r"(a[0]), "r"(a[1]), "r"(a[2]), "r"(a[3]), "r"(b[0]), "r"(b[1]));
}

// ---------------- QKV GEMM (TF32 tensor core, cp.async W pipeline) ------------
constexpr int XS = 132;            // xs row stride
constexpr int WSS = 136;           // W slab row stride
constexpr int SLABF = 32 * WSS;    // floats per slab buffer
constexpr int GEMM_SMEM = (128 * XS + 2 * SLABF) * 4;   // 102400 B

__device__ __forceinline__ void cpasync_w_slab(const float* Wsrc, float* buf,
                                               int tid) {
    unsigned sb = (unsigned)__cvta_generic_to_shared(buf);
#pragma unroll
    for (int i = 0; i < 4; ++i) {
        int idx = tid + i * 256;
        int kr = idx >> 5, c = (idx & 31) << 2;
        unsigned sa = sb + (unsigned)((kr * WSS + c) * 4);
        asm volatile("cp.async.cg.shared.global [%0], [%1], 16;\n"
                     :: "r"(sa), "l"(Wsrc + (size_t)kr * DD + c));
    }
}

__global__ __launch_bounds__(256, 2) void qkv_gemm_tc(
    const float* __restrict__ x,
    const float* __restrict__ Wq, const float* __restrict__ bq,
    const float* __restrict__ Wk, const float* __restrict__ bk,
    const float* __restrict__ Wv, const float* __restrict__ bv,
    int n)
{
    extern __shared__ float smem[];
    float* xs  = smem;               // [128 rows][XS]  tf32 values
    float* wsb = smem + 128 * XS;    // [2][32 k][WSS]  W slab double buffer

    const int tid  = threadIdx.x;
    const int lane = tid & 31;
    const int wid  = tid >> 5;
    const int warpM = wid & 3;
    const int warpN = wid >> 2;
    const int row0 = blockIdx.x * 128;

    for (int i = tid; i < 128 * 32; i += 256) {
        int r = i >> 5, c = (i & 31) << 2;
        float4 v = make_float4(0.f, 0.f, 0.f, 0.f);
        if (row0 + r < n) v = *(const float4*)(x + (size_t)(row0 + r) * DD + c);
        xs[r * XS + c]     = to_tf32(v.x);
        xs[r * XS + c + 1] = to_tf32(v.y);
        xs[r * XS + c + 2] = to_tf32(v.z);
        xs[r * XS + c + 3] = to_tf32(v.w);
    }

    const float* Ws[3] = {Wq, Wk, Wv};
    const float* Bs[3] = {bq, bk, bv};

    const int gidx = lane >> 2;
    const int tidx = lane & 3;

    cpasync_w_slab(Ws[0], wsb, tid);
    asm volatile("cp.async.commit_group;\n");

    float C[2][8][4];

#pragma unroll 1
    for (int ls = 0; ls < 12; ++ls) {
        const int w = ls >> 2;
        const int s = ls & 3;

        if (s == 0) {
#pragma unroll
            for (int mt = 0; mt < 2; ++mt)
#pragma unroll
                for (int nt = 0; nt < 8; ++nt)
#pragma unroll
                    for (int q = 0; q < 4; ++q) C[mt][nt][q] = 0.f;
        }

        asm volatile("cp.async.wait_group 0;\n");
        __syncthreads();

        if (ls < 11) {
            const int nls = ls + 1;
            cpasync_w_slab(Ws[nls >> 2] + (size_t)((nls & 3) * 32) * DD,
                           wsb + (nls & 1) * SLABF, tid);
            asm volatile("cp.async.commit_group;\n");
        }

        float* wb = wsb + (ls & 1) * SLABF;
#pragma unroll
        for (int i = 0; i < 4; ++i) {
            int idx = tid + i * 256;
            int kr = idx >> 5, c = (idx & 31) << 2;
            float4* p = (float4*)(wb + kr * WSS + c);
            float4 v = *p;
            v.x = to_tf32(v.x); v.y = to_tf32(v.y);
            v.z = to_tf32(v.z); v.w = to_tf32(v.w);
            *p = v;
        }
        __syncthreads();

#pragma unroll
        for (int k8 = 0; k8 < 4; ++k8) {
            unsigned a[2][4];
#pragma unroll
            for (int mt = 0; mt < 2; ++mt) {
                int row = warpM * 32 + mt * 16 + gidx;
                int col = s * 32 + k8 * 8 + tidx;
                a[mt][0] = __float_as_uint(xs[row * XS + col]);
                a[mt][1] = __float_as_uint(xs[(row + 8) * XS + col]);
                a[mt][2] = __float_as_uint(xs[row * XS + col + 4]);
                a[mt][3] = __float_as_uint(xs[(row + 8) * XS + col + 4]);
            }
#pragma unroll
            for (int nt = 0; nt < 8; ++nt) {
                int colb = warpN * 64 + nt * 8 + gidx;
                int krow = k8 * 8 + tidx;
                unsigned b[2];
                b[0] = __float_as_uint(wb[krow * WSS + colb]);
                b[1] = __float_as_uint(wb[(krow + 4) * WSS + colb]);
                mma_tf32(C[0][nt], a[0], b);
                mma_tf32(C[1][nt], a[1], b);
            }
        }

        if (s == 3) {
            const float* B = Bs[w];
#pragma unroll
            for (int nt = 0; nt < 8; ++nt) {
                int col = warpN * 64 + nt * 8 + 2 * tidx;
                float b0 = __ldg(B + col);
                float b1 = __ldg(B + col + 1);
#pragma unroll
                for (int mt = 0; mt < 2; ++mt) {
                    int r0 = row0 + warpM * 32 + mt * 16 + gidx;
                    int r1 = r0 + 8;
                    float o00 = C[mt][nt][0] + b0, o01 = C[mt][nt][1] + b1;
                    float o10 = C[mt][nt][2] + b0, o11 = C[mt][nt][3] + b1;
                    if (w == 0) {
                        if (r0 < n) *(float2*)(g_Q + (size_t)r0 * DD + col) =
                            make_float2(o00, o01);
                        if (r1 < n) *(float2*)(g_Q + (size_t)r1 * DD + col) =
                            make_float2(o10, o11);
                    } else {
                        int off = (w == 1) ? 0 : 128;
                        if (r0 < n)
                            *(__half2*)(g_KVh + (size_t)r0 * 256 + off + col) =
                                __floats2half2_rn(o00, o01);
                        if (r1 < n)
                            *(__half2*)(g_KVh + (size_t)r1 * 256 + off + col) =
                                __floats2half2_rn(o10, o11);
                    }
                }
            }
        }
        __syncthreads();
    }
}

// ---------------- CSR construction -------------------------------------------
__global__ void hist_kernel(const int* __restrict__ dst, int E) {
    int i = blockIdx.x * blockDim.x + threadIdx.x;
    if (i < E) atomicAdd(&g_deg[dst[i]], 1);
}

__global__ __launch_bounds__(1024) void scan1(int n) {
    __shared__ int sm[1024];
    const int t = threadIdx.x;
    const int i = blockIdx.x * 1024 + t;
    int v = (i < n) ? g_deg[i] : 0;
    if (i < n) g_deg[i] = 0;
    sm[t] = v;
    __syncthreads();
    for (int off = 1; off < 1024; off <<= 1) {
        int u = (t >= off) ? sm[t - off] : 0;
        __syncthreads();
        sm[t] += u;
        __syncthreads();
    }
    if (i < n) g_rowptr[i] = sm[t] - v;
    if (t == 1023) g_bsum[blockIdx.x] = sm[t];
}

__global__ __launch_bounds__(1024) void scan3(int n, int E) {
    __shared__ int soff;
    const int t = threadIdx.x;
    if (t == 0) soff = 0;
    __syncthreads();
    int acc = 0;
    for (int j = t; j < blockIdx.x; j += 1024) acc += g_bsum[j];
    if (acc) atomicAdd(&soff, acc);
    __syncthreads();
    const int i = blockIdx.x * 1024 + t;
    if (i < n) {
        int r = g_rowptr[i] + soff;
        g_rowptr[i] = r;
        g_cursor[i] = r;
    }
    if (i == 0) g_rowptr[n] = E;
}

__global__ void scatter_kernel(const int* __restrict__ src,
                               const int* __restrict__ dst, int E) {
    int i = blockIdx.x * blockDim.x + threadIdx.x;
    if (i < E) {
        int p = atomicAdd(&g_cursor[dst[i]], 1);
        g_edge[p] = make_int2(i, src[i]);
    }
}

// ---------------- per-node online-softmax attention + normalization ----------
// One warp per node, TWO edges per iteration (16 lanes each).
// lane4 = lane&15: head h = lane4>>1, half-sel hs = lane4&1 -> 8 dims/lane.
// slot = lane>>4 picks which of the 2 edges. Per-slot online softmax states
// merged at the end via shfl_xor(16).
__global__ __launch_bounds__(256) void node_attn(
    const float* __restrict__ pi, const float* __restrict__ view_w,
    float* __restrict__ ns_out, float* __restrict__ attn_out, int n)
{
    int warp = (blockIdx.x * blockDim.x + threadIdx.x) >> 5;
    if (warp >= n) return;
    const int lane  = threadIdx.x & 31;
    const int lane4 = lane & 15;
    const int slot  = lane >> 4;
    const int h     = lane4 >> 1;
    const int nd = warp;

    const float4* Q4  = (const float4*)g_Q;
    const uint4*  KV4 = (const uint4*)g_KVh;   // 32 uint4 per node (512B)

    // 8 q dims for (h, hs): global dims lane4*8 .. +7
    const float4 q0 = Q4[nd * 32 + lane4 * 2];
    const float4 q1 = Q4[nd * 32 + lane4 * 2 + 1];
    const float p0 = pi[nd * 24 + h * 3 + 0];
    const float p1 = pi[nd * 24 + h * 3 + 1];
    const float p2 = pi[nd * 24 + h * 3 + 2];

    const int beg = g_rowptr[nd];
    const int end = g_rowptr[nd + 1];

    float m_run = -3.0e38f;
    float s_run = 0.f;
    float acc[8];
#pragma unroll
    for (int i = 0; i < 8; ++i) acc[i] = 0.f;

    for (int j0 = beg; j0 < end; j0 += 2) {
        const int j = j0 + slot;
        const bool act = (j < end);
        const int jc = act ? j : (end - 1);
        const int2 e = g_edge[jc];
        const int eid = e.x;
        const int sN = e.y;

        uint4 ku = KV4[(size_t)sN * 32 + lane4];        // 8 K halfs
        uint4 vu = KV4[(size_t)sN * 32 + 16 + lane4];   // 8 V halfs
        float2 k0 = __half22float2(*(__half2*)&ku.x);
        float2 k1 = __half22float2(*(__half2*)&ku.y);
        float2 k2 = __half22float2(*(__half2*)&ku.z);
        float2 k3 = __half22float2(*(__half2*)&ku.w);

        float d = q0.x * k0.x + q0.y * k0.y + q0.z * k1.x + q0.w * k1.y
                + q1.x * k2.x + q1.y * k2.y + q1.z * k3.x + q1.w * k3.y;
        d += __shfl_xor_sync(0xffffffff, d, 1);   // full 16-dim dot per pair

        float vw0 = view_w[eid * 3 + 0];
        float vw1 = view_w[eid * 3 + 1];
        float vw2 = view_w[eid * 3 + 2];
        float mix = p0 * vw0 + p1 * vw1 + p2 * vw2;

        float sc = d * 0.25f + __logf(fmaxf(mix, 1e-8f));
        if (!(mix > 0.f)) sc = -1e9f;

        if (act) {
            if ((lane4 & 1) == 0) g_scores[(size_t)j * HH + h] = sc;
            float nm = fmaxf(m_run, sc);
            float scale = __expf(m_run - nm);
            float p = (sc > -1e8f) ? __expf(sc - nm) : 0.f;
            float2 v0 = __half22float2(*(__half2*)&vu.x);
            float2 v1 = __half22float2(*(__half2*)&vu.y);
            float2 v2 = __half22float2(*(__half2*)&vu.z);
            float2 v3 = __half22float2(*(__half2*)&vu.w);
            s_run = s_run * scale + p;
            acc[0] = acc[0] * scale + p * v0.x;
            acc[1] = acc[1] * scale + p * v0.y;
            acc[2] = acc[2] * scale + p * v1.x;
            acc[3] = acc[3] * scale + p * v1.y;
            acc[4] = acc[4] * scale + p * v2.x;
            acc[5] = acc[5] * scale + p * v2.y;
            acc[6] = acc[6] * scale + p * v3.x;
            acc[7] = acc[7] * scale + p * v3.y;
            m_run = nm;
        }
    }

    // merge the two slots (shfl across lane bit 4)
    float m_o = __shfl_xor_sync(0xffffffff, m_run, 16);
    float s_o = __shfl_xor_sync(0xffffffff, s_run, 16);
    float m_t = fmaxf(m_run, m_o);
    float f_s = __expf(m_run - m_t);
    float f_o = __expf(m_o - m_t);
    float s_tot = s_run * f_s + s_o * f_o;
#pragma unroll
    for (int i = 0; i < 8; ++i) {
        float a_o = __shfl_xor_sync(0xffffffff, acc[i], 16);
        acc[i] = acc[i] * f_s + a_o * f_o;
    }
    float inv = 1.f / fmaxf(s_tot, 1e-8f);

    if (slot == 0) {
        float4 o0 = make_float4(acc[0] * inv, acc[1] * inv,
                                acc[2] * inv, acc[3] * inv);
        float4 o1 = make_float4(acc[4] * inv, acc[5] * inv,
                                acc[6] * inv, acc[7] * inv);
        ((float4*)ns_out)[nd * 32 + lane4 * 2]     = o0;
        ((float4*)ns_out)[nd * 32 + lane4 * 2 + 1] = o1;
    }

    // sweep 2: normalize scores -> attn_out. 4 edges per iteration.
    const int h2 = lane & 7;
    const float m_h = __shfl_sync(0xffffffff, m_t, h2 << 1);  // lane4 = 2*h2 has head h2
    const float i_h = __shfl_sync(0xffffffff, inv, h2 << 1);
    for (int j0 = beg; j0 < end; j0 += 4) {
        int j = j0 + (lane >> 3);
        if (j < end) {
            int eid = g_edge[j].x;
            float sc = g_scores[(size_t)j * HH + h2];
            float a = (sc > -1e8f) ? __expf(sc - m_h) * i_h : 0.f;
            attn_out[(size_t)eid * HH + h2] = a;
        }
    }
}

// ---------------- launch ------------------------------------------------------
extern "C" void kernel_launch(void* const* d_in, const int* in_sizes, int n_in,
                              void* d_out, int out_size) {
    const float* x   = (const float*)d_in[0];
    const float* pi  = (const float*)d_in[1];
    const float* vw  = (const float*)d_in[2];
    const float* Wq  = (const float*)d_in[3];
    const float* bq  = (const float*)d_in[4];
    const float* Wk  = (const float*)d_in[5];
    const float* bk  = (const float*)d_in[6];
    const float* Wv  = (const float*)d_in[7];
    const float* bv  = (const float*)d_in[8];
    const int*   src = (const int*)d_in[9];
    const int*   dst = (const int*)d_in[10];

    const int n = in_sizes[0] / DD;   // 100000
    const int E = in_sizes[9];        // 1600000

    float* out = (float*)d_out;
    float* ns_out = out;                          // [n, H, DH]
    float* attn_out = out + (size_t)n * DD;       // [E, H]

    cudaFuncSetAttribute(qkv_gemm_tc, cudaFuncAttributeMaxDynamicSharedMemorySize,
                         GEMM_SMEM);

    const int nb = (n + 1023) / 1024;
    hist_kernel<<<(E + 255) / 256, 256>>>(dst, E);
    scan1<<<nb, 1024>>>(n);
    scan3<<<nb, 1024>>>(n, E);
    qkv_gemm_tc<<<(n + 127) / 128, 256, GEMM_SMEM>>>(x, Wq, bq, Wk, bk, Wv, bv, n);  // 4th: profiled
    scatter_kernel<<<(E + 255) / 256, 256>>>(src, dst, E);

    node_attn<<<(n + 7) / 8, 256>>>(pi, vw, ns_out, attn_out, n);
}

// round 9
// speedup vs baseline: 1.0323x; 1.0323x over previous
#include <cuda_runtime.h>
#include <cuda_fp16.h>
#include <math_constants.h>

// Problem constants (fixed by the dataset)
constexpr int NN = 100000;   // nodes
constexpr int EE = 1600000;  // edges
constexpr int DD = 128;      // model dim
constexpr int HH = 8;        // heads
// DH = 16, M = 3

// ---------------- scratch (static device globals; no allocation) -------------
__device__ float  g_Q[NN * DD];
__device__ __half g_KVh[NN * 256];    // per node: K[128 halfs] then V[128 halfs]
__device__ int    g_deg[NN];
__device__ int    g_rowptr[NN + 1];
__device__ int    g_cursor[NN];
__device__ int2   g_edge[EE];         // (eid, src) packed
__device__ float  g_scores[(size_t)EE * HH];  // raw scores in CSR order
__device__ int    g_bsum[128];

// ---------------- TF32 helpers ------------------------------------------------
__device__ __forceinline__ float to_tf32(float a) {
    float r; asm("cvt.rna.tf32.f32 %0, %1;" : "=f"(r) : "f"(a)); return r;
}

__device__ __forceinline__ void mma_tf32(float c[4], const unsigned a[4],
                                         const unsigned b[2]) {
    asm volatile(
        "mma.sync.aligned.m16n8k8.row.col.f32.tf32.tf32.f32 "
        "{%0,%1,%2,%3}, {%4,%5,%6,%7}, {%8,%9}, {%0,%1,%2,%3};"
        : "+f"(c[0]), "+f"(c[1]), "+f"(c[2]), "+f"(c[3])
        : "r"(a[0]), "r"(a[1]), "r"(a[2]), "r"(a[3]), "r"(b[0]), "r"(b[1]));
}

// ---------------- QKV GEMM (TF32 tensor core, cp.async W pipeline) ------------
constexpr int XS = 132;            // xs row stride
constexpr int WSS = 136;           // W slab row stride
constexpr int SLABF = 32 * WSS;    // floats per slab buffer
constexpr int GEMM_SMEM = (128 * XS + 2 * SLABF) * 4;   // 102400 B

__device__ __forceinline__ void cpasync_w_slab(const float* Wsrc, float* buf,
                                               int tid) {
    unsigned sb = (unsigned)__cvta_generic_to_shared(buf);
#pragma unroll
    for (int i = 0; i < 4; ++i) {
        int idx = tid + i * 256;
        int kr = idx >> 5, c = (idx & 31) << 2;
        unsigned sa = sb + (unsigned)((kr * WSS + c) * 4);
        asm volatile("cp.async.cg.shared.global [%0], [%1], 16;\n"
                     :: "r"(sa), "l"(Wsrc + (size_t)kr * DD + c));
    }
}

__global__ __launch_bounds__(256, 2) void qkv_gemm_tc(
    const float* __restrict__ x,
    const float* __restrict__ Wq, const float* __restrict__ bq,
    const float* __restrict__ Wk, const float* __restrict__ bk,
    const float* __restrict__ Wv, const float* __restrict__ bv,
    int n)
{
    extern __shared__ float smem[];
    float* xs  = smem;               // [128 rows][XS]  tf32 values
    float* wsb = smem + 128 * XS;    // [2][32 k][WSS]  W slab double buffer

    const int tid  = threadIdx.x;
    const int lane = tid & 31;
    const int wid  = tid >> 5;
    const int warpM = wid & 3;
    const int warpN = wid >> 2;
    const int row0 = blockIdx.x * 128;

    for (int i = tid; i < 128 * 32; i += 256) {
        int r = i >> 5, c = (i & 31) << 2;
        float4 v = make_float4(0.f, 0.f, 0.f, 0.f);
        if (row0 + r < n) v = *(const float4*)(x + (size_t)(row0 + r) * DD + c);
        xs[r * XS + c]     = to_tf32(v.x);
        xs[r * XS + c + 1] = to_tf32(v.y);
        xs[r * XS + c + 2] = to_tf32(v.z);
        xs[r * XS + c + 3] = to_tf32(v.w);
    }

    const float* Ws[3] = {Wq, Wk, Wv};
    const float* Bs[3] = {bq, bk, bv};

    const int gidx = lane >> 2;
    const int tidx = lane & 3;

    cpasync_w_slab(Ws[0], wsb, tid);
    asm volatile("cp.async.commit_group;\n");

    float C[2][8][4];

#pragma unroll 1
    for (int ls = 0; ls < 12; ++ls) {
        const int w = ls >> 2;
        const int s = ls & 3;

        if (s == 0) {
#pragma unroll
            for (int mt = 0; mt < 2; ++mt)
#pragma unroll
                for (int nt = 0; nt < 8; ++nt)
#pragma unroll
                    for (int q = 0; q < 4; ++q) C[mt][nt][q] = 0.f;
        }

        asm volatile("cp.async.wait_group 0;\n");
        __syncthreads();

        if (ls < 11) {
            const int nls = ls + 1;
            cpasync_w_slab(Ws[nls >> 2] + (size_t)((nls & 3) * 32) * DD,
                           wsb + (nls & 1) * SLABF, tid);
            asm volatile("cp.async.commit_group;\n");
        }

        float* wb = wsb + (ls & 1) * SLABF;
#pragma unroll
        for (int i = 0; i < 4; ++i) {
            int idx = tid + i * 256;
            int kr = idx >> 5, c = (idx & 31) << 2;
            float4* p = (float4*)(wb + kr * WSS + c);
            float4 v = *p;
            v.x = to_tf32(v.x); v.y = to_tf32(v.y);
            v.z = to_tf32(v.z); v.w = to_tf32(v.w);
            *p = v;
        }
        __syncthreads();

#pragma unroll
        for (int k8 = 0; k8 < 4; ++k8) {
            unsigned a[2][4];
#pragma unroll
            for (int mt = 0; mt < 2; ++mt) {
                int row = warpM * 32 + mt * 16 + gidx;
                int col = s * 32 + k8 * 8 + tidx;
                a[mt][0] = __float_as_uint(xs[row * XS + col]);
                a[mt][1] = __float_as_uint(xs[(row + 8) * XS + col]);
                a[mt][2] = __float_as_uint(xs[row * XS + col + 4]);
                a[mt][3] = __float_as_uint(xs[(row + 8) * XS + col + 4]);
            }
#pragma unroll
            for (int nt = 0; nt < 8; ++nt) {
                int colb = warpN * 64 + nt * 8 + gidx;
                int krow = k8 * 8 + tidx;
                unsigned b[2];
                b[0] = __float_as_uint(wb[krow * WSS + colb]);
                b[1] = __float_as_uint(wb[(krow + 4) * WSS + colb]);
                mma_tf32(C[0][nt], a[0], b);
                mma_tf32(C[1][nt], a[1], b);
            }
        }

        if (s == 3) {
            const float* B = Bs[w];
#pragma unroll
            for (int nt = 0; nt < 8; ++nt) {
                int col = warpN * 64 + nt * 8 + 2 * tidx;
                float b0 = __ldg(B + col);
                float b1 = __ldg(B + col + 1);
#pragma unroll
                for (int mt = 0; mt < 2; ++mt) {
                    int r0 = row0 + warpM * 32 + mt * 16 + gidx;
                    int r1 = r0 + 8;
                    float o00 = C[mt][nt][0] + b0, o01 = C[mt][nt][1] + b1;
                    float o10 = C[mt][nt][2] + b0, o11 = C[mt][nt][3] + b1;
                    if (w == 0) {
                        if (r0 < n) *(float2*)(g_Q + (size_t)r0 * DD + col) =
                            make_float2(o00, o01);
                        if (r1 < n) *(float2*)(g_Q + (size_t)r1 * DD + col) =
                            make_float2(o10, o11);
                    } else {
                        int off = (w == 1) ? 0 : 128;
                        if (r0 < n)
                            *(__half2*)(g_KVh + (size_t)r0 * 256 + off + col) =
                                __floats2half2_rn(o00, o01);
                        if (r1 < n)
                            *(__half2*)(g_KVh + (size_t)r1 * 256 + off + col) =
                                __floats2half2_rn(o10, o11);
                    }
                }
            }
        }
        __syncthreads();
    }
}

// ---------------- CSR construction -------------------------------------------
__global__ void hist_kernel(const int* __restrict__ dst, int E) {
    int i = blockIdx.x * blockDim.x + threadIdx.x;
    if (i < E) atomicAdd(&g_deg[dst[i]], 1);
}

__global__ __launch_bounds__(1024) void scan1(int n) {
    __shared__ int sm[1024];
    const int t = threadIdx.x;
    const int i = blockIdx.x * 1024 + t;
    int v = (i < n) ? g_deg[i] : 0;
    if (i < n) g_deg[i] = 0;
    sm[t] = v;
    __syncthreads();
    for (int off = 1; off < 1024; off <<= 1) {
        int u = (t >= off) ? sm[t - off] : 0;
        __syncthreads();
        sm[t] += u;
        __syncthreads();
    }
    if (i < n) g_rowptr[i] = sm[t] - v;
    if (t == 1023) g_bsum[blockIdx.x] = sm[t];
}

__global__ __launch_bounds__(1024) void scan3(int n, int E) {
    __shared__ int soff;
    const int t = threadIdx.x;
    if (t == 0) soff = 0;
    __syncthreads();
    int acc = 0;
    for (int j = t; j < blockIdx.x; j += 1024) acc += g_bsum[j];
    if (acc) atomicAdd(&soff, acc);
    __syncthreads();
    const int i = blockIdx.x * 1024 + t;
    if (i < n) {
        int r = g_rowptr[i] + soff;
        g_rowptr[i] = r;
        g_cursor[i] = r;
    }
    if (i == 0) g_rowptr[n] = E;
}

__global__ void scatter_kernel(const int* __restrict__ src,
                               const int* __restrict__ dst, int E) {
    int i = blockIdx.x * blockDim.x + threadIdx.x;
    if (i < E) {
        int p = atomicAdd(&g_cursor[dst[i]], 1);
        g_edge[p] = make_int2(i, src[i]);
    }
}

// ---------------- per-node online-softmax attention + normalization ----------
// One warp per node, FOUR edges per iteration. lane = slot*8 + head:
// each lane owns a full 16-dim head -> complete q.k dot in-lane, ZERO inner
// shfls. Per-slot softmax states merged once at the end (shfl_xor 8, 16).
__global__ __launch_bounds__(256) void node_attn(
    const float* __restrict__ pi, const float* __restrict__ view_w,
    float* __restrict__ ns_out, float* __restrict__ attn_out, int n)
{
    int warp = (blockIdx.x * blockDim.x + threadIdx.x) >> 5;
    if (warp >= n) return;
    const int lane = threadIdx.x & 31;
    const int slot = lane >> 3;     // 0..3  edge slot
    const int h    = lane & 7;      // head
    const int nd = warp;

    const float4* Q4  = (const float4*)g_Q;
    const uint4*  KV4 = (const uint4*)g_KVh;   // 32 uint4 per node (512B)

    // full 16-dim q for head h (broadcast across the 4 slots)
    const float4 q0 = Q4[nd * 32 + h * 4 + 0];
    const float4 q1 = Q4[nd * 32 + h * 4 + 1];
    const float4 q2 = Q4[nd * 32 + h * 4 + 2];
    const float4 q3 = Q4[nd * 32 + h * 4 + 3];
    const float p0 = pi[nd * 24 + h * 3 + 0];
    const float p1 = pi[nd * 24 + h * 3 + 1];
    const float p2 = pi[nd * 24 + h * 3 + 2];

    const int beg = g_rowptr[nd];
    const int end = g_rowptr[nd + 1];

    float m_run = -3.0e38f;
    float s_run = 0.f;
    float acc[16];
#pragma unroll
    for (int i = 0; i < 16; ++i) acc[i] = 0.f;

    for (int j0 = beg; j0 < end; j0 += 4) {
        const int j = j0 + slot;
        if (j < end) {
            const int2 e = g_edge[j];
            const int eid = e.x;
            const int sN = e.y;
            const uint4* kv = KV4 + (size_t)sN * 32;

            uint4 ka = kv[h * 2];           // K halfs 0..7 of head h
            uint4 kb = kv[h * 2 + 1];       // K halfs 8..15
            float2 t;
            t = __half22float2(*(__half2*)&ka.x);
            float d = q0.x * t.x + q0.y * t.y;
            t = __half22float2(*(__half2*)&ka.y);
            d += q0.z * t.x + q0.w * t.y;
            t = __half22float2(*(__half2*)&ka.z);
            d += q1.x * t.x + q1.y * t.y;
            t = __half22float2(*(__half2*)&ka.w);
            d += q1.z * t.x + q1.w * t.y;
            t = __half22float2(*(__half2*)&kb.x);
            d += q2.x * t.x + q2.y * t.y;
            t = __half22float2(*(__half2*)&kb.y);
            d += q2.z * t.x + q2.w * t.y;
            t = __half22float2(*(__half2*)&kb.z);
            d += q3.x * t.x + q3.y * t.y;
            t = __half22float2(*(__half2*)&kb.w);
            d += q3.z * t.x + q3.w * t.y;

            float vw0 = view_w[eid * 3 + 0];
            float vw1 = view_w[eid * 3 + 1];
            float vw2 = view_w[eid * 3 + 2];
            float mix = p0 * vw0 + p1 * vw1 + p2 * vw2;

            float sc = d * 0.25f + __logf(fmaxf(mix, 1e-8f));
            if (!(mix > 0.f)) sc = -1e9f;
            g_scores[(size_t)j * HH + h] = sc;   // 128B contiguous per iter

            float nm = fmaxf(m_run, sc);
            float scale = __expf(m_run - nm);
            float p = (sc > -1e8f) ? __expf(sc - nm) : 0.f;
            s_run = s_run * scale + p;

            uint4 va = kv[16 + h * 2];
            uint4 vb = kv[16 + h * 2 + 1];
            t = __half22float2(*(__half2*)&va.x);
            acc[0]  = acc[0]  * scale + p * t.x;
            acc[1]  = acc[1]  * scale + p * t.y;
            t = __half22float2(*(__half2*)&va.y);
            acc[2]  = acc[2]  * scale + p * t.x;
            acc[3]  = acc[3]  * scale + p * t.y;
            t = __half22float2(*(__half2*)&va.z);
            acc[4]  = acc[4]  * scale + p * t.x;
            acc[5]  = acc[5]  * scale + p * t.y;
            t = __half22float2(*(__half2*)&va.w);
            acc[6]  = acc[6]  * scale + p * t.x;
            acc[7]  = acc[7]  * scale + p * t.y;
            t = __half22float2(*(__half2*)&vb.x);
            acc[8]  = acc[8]  * scale + p * t.x;
            acc[9]  = acc[9]  * scale + p * t.y;
            t = __half22float2(*(__half2*)&vb.y);
            acc[10] = acc[10] * scale + p * t.x;
            acc[11] = acc[11] * scale + p * t.y;
            t = __half22float2(*(__half2*)&vb.z);
            acc[12] = acc[12] * scale + p * t.x;
            acc[13] = acc[13] * scale + p * t.y;
            t = __half22float2(*(__half2*)&vb.w);
            acc[14] = acc[14] * scale + p * t.x;
            acc[15] = acc[15] * scale + p * t.y;
            m_run = nm;
        }
    }

    // merge the 4 slots (symmetric shfl_xor: all lanes end with merged state)
#pragma unroll
    for (int off = 8; off <= 16; off <<= 1) {
        float m_o = __shfl_xor_sync(0xffffffff, m_run, off);
        float s_o = __shfl_xor_sync(0xffffffff, s_run, off);
        float m_t = fmaxf(m_run, m_o);
        float f_s = __expf(m_run - m_t);
        float f_o = __expf(m_o - m_t);
        s_run = s_run * f_s + s_o * f_o;
#pragma unroll
        for (int i = 0; i < 16; ++i) {
            float a_o = __shfl_xor_sync(0xffffffff, acc[i], off);
            acc[i] = acc[i] * f_s + a_o * f_o;
        }
        m_run = m_t;
    }
    float inv = 1.f / fmaxf(s_run, 1e-8f);

    if (slot == 0) {
        float4* o = (float4*)(ns_out + (size_t)nd * DD + h * 16);
        o[0] = make_float4(acc[0] * inv, acc[1] * inv, acc[2] * inv, acc[3] * inv);
        o[1] = make_float4(acc[4] * inv, acc[5] * inv, acc[6] * inv, acc[7] * inv);
        o[2] = make_float4(acc[8] * inv, acc[9] * inv, acc[10] * inv, acc[11] * inv);
        o[3] = make_float4(acc[12] * inv, acc[13] * inv, acc[14] * inv, acc[15] * inv);
    }

    // sweep 2: normalize scores -> attn_out. 4 edges per iteration.
    const int h2 = lane & 7;
    const float m_h = __shfl_sync(0xffffffff, m_run, h2);  // lane h2 holds head h2
    const float i_h = __shfl_sync(0xffffffff, inv,   h2);
    for (int j0 = beg; j0 < end; j0 += 4) {
        int j = j0 + (lane >> 3);
        if (j < end) {
            int eid = g_edge[j].x;
            float sc = g_scores[(size_t)j * HH + h2];
            float a = (sc > -1e8f) ? __expf(sc - m_h) * i_h : 0.f;
            attn_out[(size_t)eid * HH + h2] = a;
        }
    }
}

// ---------------- launch ------------------------------------------------------
extern "C" void kernel_launch(void* const* d_in, const int* in_sizes, int n_in,
                              void* d_out, int out_size) {
    const float* x   = (const float*)d_in[0];
    const float* pi  = (const float*)d_in[1];
    const float* vw  = (const float*)d_in[2];
    const float* Wq  = (const float*)d_in[3];
    const float* bq  = (const float*)d_in[4];
    const float* Wk  = (const float*)d_in[5];
    const float* bk  = (const float*)d_in[6];
    const float* Wv  = (const float*)d_in[7];
    const float* bv  = (const float*)d_in[8];
    const int*   src = (const int*)d_in[9];
    const int*   dst = (const int*)d_in[10];

    const int n = in_sizes[0] / DD;   // 100000
    const int E = in_sizes[9];        // 1600000

    float* out = (float*)d_out;
    float* ns_out = out;                          // [n, H, DH]
    float* attn_out = out + (size_t)n * DD;       // [E, H]

    cudaFuncSetAttribute(qkv_gemm_tc, cudaFuncAttributeMaxDynamicSharedMemorySize,
                         GEMM_SMEM);

    const int nb = (n + 1023) / 1024;
    hist_kernel<<<(E + 255) / 256, 256>>>(dst, E);
    scan1<<<nb, 1024>>>(n);
    scan3<<<nb, 1024>>>(n, E);
    qkv_gemm_tc<<<(n + 127) / 128, 256, GEMM_SMEM>>>(x, Wq, bq, Wk, bk, Wv, bv, n);  // 4th: profiled
    scatter_kernel<<<(E + 255) / 256, 256>>>(src, dst, E);

    node_attn<<<(n + 7) / 8, 256>>>(pi, vw, ns_out, attn_out, n);
}

// round 11
// speedup vs baseline: 1.0717x; 1.0381x over previous
#include <cuda_runtime.h>
#include <cuda_fp16.h>
#include <math_constants.h>

// Problem constants (fixed by the dataset)
constexpr int NN = 100000;   // nodes
constexpr int EE = 1600000;  // edges
constexpr int DD = 128;      // model dim
constexpr int HH = 8;        // heads
// DH = 16, M = 3

// ---------------- scratch (static device globals; no allocation) -------------
__device__ float  g_Q[NN * DD];
__device__ __half g_KVh[NN * 256];    // per node: K[128 halfs] then V[128 halfs]
__device__ int    g_deg[NN];
__device__ int    g_rowptr[NN + 1];
__device__ int    g_cursor[NN];
__device__ int2   g_edge[EE];         // (eid, src) packed
__device__ float  g_scores[(size_t)EE * HH];  // raw scores in CSR order
__device__ int    g_bsum[128];

// ---------------- TF32 helpers ------------------------------------------------
__device__ __forceinline__ float to_tf32(float a) {
    float r; asm("cvt.rna.tf32.f32 %0, %1;" : "=f"(r) : "f"(a)); return r;
}

__device__ __forceinline__ void mma_tf32(float c[4], const unsigned a[4],
                                         const unsigned b[2]) {
    asm volatile(
        "mma.sync.aligned.m16n8k8.row.col.f32.tf32.tf32.f32 "
        "{%0,%1,%2,%3}, {%4,%5,%6,%7}, {%8,%9}, {%0,%1,%2,%3};"
        : "+f"(c[0]), "+f"(c[1]), "+f"(c[2]), "+f"(c[3])
        : "r"(a[0]), "r"(a[1]), "r"(a[2]), "r"(a[3]), "r"(b[0]), "r"(b[1]));
}

// ---------------- QKV GEMM (TF32 tensor core, cp.async W pipeline) ------------
constexpr int XS = 132;            // xs row stride
constexpr int WSS = 136;           // W slab row stride
constexpr int SLABF = 32 * WSS;    // floats per slab buffer
constexpr int GEMM_SMEM = (128 * XS + 2 * SLABF) * 4;   // 102400 B

__device__ __forceinline__ void cpasync_w_slab(const float* Wsrc, float* buf,
                                               int tid) {
    unsigned sb = (unsigned)__cvta_generic_to_shared(buf);
#pragma unroll
    for (int i = 0; i < 4; ++i) {
        int idx = tid + i * 256;
        int kr = idx >> 5, c = (idx & 31) << 2;
        unsigned sa = sb + (unsigned)((kr * WSS + c) * 4);
        asm volatile("cp.async.cg.shared.global [%0], [%1], 16;\n"
                     :: "r"(sa), "l"(Wsrc + (size_t)kr * DD + c));
    }
}

__global__ __launch_bounds__(256, 2) void qkv_gemm_tc(
    const float* __restrict__ x,
    const float* __restrict__ Wq, const float* __restrict__ bq,
    const float* __restrict__ Wk, const float* __restrict__ bk,
    const float* __restrict__ Wv, const float* __restrict__ bv,
    int n)
{
    extern __shared__ float smem[];
    float* xs  = smem;               // [128 rows][XS]  tf32 values
    float* wsb = smem + 128 * XS;    // [2][32 k][WSS]  W slab double buffer

    const int tid  = threadIdx.x;
    const int lane = tid & 31;
    const int wid  = tid >> 5;
    const int warpM = wid & 3;
    const int warpN = wid >> 2;
    const int row0 = blockIdx.x * 128;

    for (int i = tid; i < 128 * 32; i += 256) {
        int r = i >> 5, c = (i & 31) << 2;
        float4 v = make_float4(0.f, 0.f, 0.f, 0.f);
        if (row0 + r < n) v = *(const float4*)(x + (size_t)(row0 + r) * DD + c);
        xs[r * XS + c]     = to_tf32(v.x);
        xs[r * XS + c + 1] = to_tf32(v.y);
        xs[r * XS + c + 2] = to_tf32(v.z);
        xs[r * XS + c + 3] = to_tf32(v.w);
    }

    const float* Ws[3] = {Wq, Wk, Wv};
    const float* Bs[3] = {bq, bk, bv};

    const int gidx = lane >> 2;
    const int tidx = lane & 3;

    cpasync_w_slab(Ws[0], wsb, tid);
    asm volatile("cp.async.commit_group;\n");

    float C[2][8][4];

#pragma unroll 1
    for (int ls = 0; ls < 12; ++ls) {
        const int w = ls >> 2;
        const int s = ls & 3;

        if (s == 0) {
#pragma unroll
            for (int mt = 0; mt < 2; ++mt)
#pragma unroll
                for (int nt = 0; nt < 8; ++nt)
#pragma unroll
                    for (int q = 0; q < 4; ++q) C[mt][nt][q] = 0.f;
        }

        asm volatile("cp.async.wait_group 0;\n");
        __syncthreads();

        if (ls < 11) {
            const int nls = ls + 1;
            cpasync_w_slab(Ws[nls >> 2] + (size_t)((nls & 3) * 32) * DD,
                           wsb + (nls & 1) * SLABF, tid);
            asm volatile("cp.async.commit_group;\n");
        }

        float* wb = wsb + (ls & 1) * SLABF;
#pragma unroll
        for (int i = 0; i < 4; ++i) {
            int idx = tid + i * 256;
            int kr = idx >> 5, c = (idx & 31) << 2;
            float4* p = (float4*)(wb + kr * WSS + c);
            float4 v = *p;
            v.x = to_tf32(v.x); v.y = to_tf32(v.y);
            v.z = to_tf32(v.z); v.w = to_tf32(v.w);
            *p = v;
        }
        __syncthreads();

#pragma unroll
        for (int k8 = 0; k8 < 4; ++k8) {
            unsigned a[2][4];
#pragma unroll
            for (int mt = 0; mt < 2; ++mt) {
                int row = warpM * 32 + mt * 16 + gidx;
                int col = s * 32 + k8 * 8 + tidx;
                a[mt][0] = __float_as_uint(xs[row * XS + col]);
                a[mt][1] = __float_as_uint(xs[(row + 8) * XS + col]);
                a[mt][2] = __float_as_uint(xs[row * XS + col + 4]);
                a[mt][3] = __float_as_uint(xs[(row + 8) * XS + col + 4]);
            }
#pragma unroll
            for (int nt = 0; nt < 8; ++nt) {
                int colb = warpN * 64 + nt * 8 + gidx;
                int krow = k8 * 8 + tidx;
                unsigned b[2];
                b[0] = __float_as_uint(wb[krow * WSS + colb]);
                b[1] = __float_as_uint(wb[(krow + 4) * WSS + colb]);
                mma_tf32(C[0][nt], a[0], b);
                mma_tf32(C[1][nt], a[1], b);
            }
        }

        if (s == 3) {
            const float* B = Bs[w];
#pragma unroll
            for (int nt = 0; nt < 8; ++nt) {
                int col = warpN * 64 + nt * 8 + 2 * tidx;
                float b0 = __ldg(B + col);
                float b1 = __ldg(B + col + 1);
#pragma unroll
                for (int mt = 0; mt < 2; ++mt) {
                    int r0 = row0 + warpM * 32 + mt * 16 + gidx;
                    int r1 = r0 + 8;
                    float o00 = C[mt][nt][0] + b0, o01 = C[mt][nt][1] + b1;
                    float o10 = C[mt][nt][2] + b0, o11 = C[mt][nt][3] + b1;
                    if (w == 0) {
                        if (r0 < n) *(float2*)(g_Q + (size_t)r0 * DD + col) =
                            make_float2(o00, o01);
                        if (r1 < n) *(float2*)(g_Q + (size_t)r1 * DD + col) =
                            make_float2(o10, o11);
                    } else {
                        int off = (w == 1) ? 0 : 128;
                        if (r0 < n)
                            *(__half2*)(g_KVh + (size_t)r0 * 256 + off + col) =
                                __floats2half2_rn(o00, o01);
                        if (r1 < n)
                            *(__half2*)(g_KVh + (size_t)r1 * 256 + off + col) =
                                __floats2half2_rn(o10, o11);
                    }
                }
            }
        }
        __syncthreads();
    }
}

// ---------------- CSR construction -------------------------------------------
__global__ void hist_kernel(const int* __restrict__ dst, int E) {
    int i = blockIdx.x * blockDim.x + threadIdx.x;
    if (i < E) atomicAdd(&g_deg[dst[i]], 1);
}

__global__ __launch_bounds__(1024) void scan1(int n) {
    __shared__ int sm[1024];
    const int t = threadIdx.x;
    const int i = blockIdx.x * 1024 + t;
    int v = (i < n) ? g_deg[i] : 0;
    if (i < n) g_deg[i] = 0;
    sm[t] = v;
    __syncthreads();
    for (int off = 1; off < 1024; off <<= 1) {
        int u = (t >= off) ? sm[t - off] : 0;
        __syncthreads();
        sm[t] += u;
        __syncthreads();
    }
    if (i < n) g_rowptr[i] = sm[t] - v;
    if (t == 1023) g_bsum[blockIdx.x] = sm[t];
}

__global__ __launch_bounds__(1024) void scan3(int n, int E) {
    __shared__ int soff;
    const int t = threadIdx.x;
    if (t == 0) soff = 0;
    __syncthreads();
    int acc = 0;
    for (int j = t; j < blockIdx.x; j += 1024) acc += g_bsum[j];
    if (acc) atomicAdd(&soff, acc);
    __syncthreads();
    const int i = blockIdx.x * 1024 + t;
    if (i < n) {
        int r = g_rowptr[i] + soff;
        g_rowptr[i] = r;
        g_cursor[i] = r;
    }
    if (i == 0) g_rowptr[n] = E;
}

__global__ void scatter_kernel(const int* __restrict__ src,
                               const int* __restrict__ dst, int E) {
    int i = blockIdx.x * blockDim.x + threadIdx.x;
    if (i < E) {
        int p = atomicAdd(&g_cursor[dst[i]], 1);
        g_edge[p] = make_int2(i, src[i]);
    }
}

// ---------------- per-node online-softmax attention + normalization ----------
// One warp per node (R7-proven layout). Sweep 1: lane -> (head = lane/4,
// dim-quad = lane%4); scores to g_scores in CSR order. Sweep 2: normalize.
__global__ __launch_bounds__(256) void node_attn(
    const float* __restrict__ pi, const float* __restrict__ view_w,
    float* __restrict__ ns_out, float* __restrict__ attn_out, int n)
{
    int warp = (blockIdx.x * blockDim.x + threadIdx.x) >> 5;
    if (warp >= n) return;
    const int lane = threadIdx.x & 31;
    const int h = lane >> 2;
    const int nd = warp;
    const int dsub = lane & 3;

    const float4* Q4 = (const float4*)g_Q;
    const uint2* KVu = (const uint2*)g_KVh;   // 64 uint2 per node (512B)

    const float4 qv = Q4[nd * 32 + lane];
    const float p0 = pi[nd * 24 + h * 3 + 0];
    const float p1 = pi[nd * 24 + h * 3 + 1];
    const float p2 = pi[nd * 24 + h * 3 + 2];

    const int beg = g_rowptr[nd];
    const int end = g_rowptr[nd + 1];

    float m_run = -CUDART_INF_F;
    float s_run = 0.f;
    float ax = 0.f, ay = 0.f, az = 0.f, aw = 0.f;

    for (int j = beg; j < end; ++j) {
        const int2 e = g_edge[j];
        const int eid = e.x;
        const int sN = e.y;

        uint2 ku = KVu[(size_t)sN * 64 + lane];
        uint2 vu = KVu[(size_t)sN * 64 + 32 + lane];
        float2 k01 = __half22float2(*(__half2*)&ku.x);
        float2 k23 = __half22float2(*(__half2*)&ku.y);

        float d = qv.x * k01.x + qv.y * k01.y + qv.z * k23.x + qv.w * k23.y;
        d += __shfl_xor_sync(0xffffffff, d, 1);
        d += __shfl_xor_sync(0xffffffff, d, 2);

        float vw0 = view_w[eid * 3 + 0];
        float vw1 = view_w[eid * 3 + 1];
        float vw2 = view_w[eid * 3 + 2];
        float mix = p0 * vw0 + p1 * vw1 + p2 * vw2;

        float sc = d * 0.25f + __logf(fmaxf(mix, 1e-8f));
        if (!(mix > 0.f)) sc = -1e9f;
        if (dsub == 0) g_scores[(size_t)j * HH + h] = sc;   // sequential write

        float nm = fmaxf(m_run, sc);
        float scale = __expf(m_run - nm);
        float p = (sc > -1e8f) ? __expf(sc - nm) : 0.f;
        float2 v01 = __half22float2(*(__half2*)&vu.x);
        float2 v23 = __half22float2(*(__half2*)&vu.y);
        s_run = s_run * scale + p;
        ax = ax * scale + p * v01.x;
        ay = ay * scale + p * v01.y;
        az = az * scale + p * v23.x;
        aw = aw * scale + p * v23.y;
        m_run = nm;
    }

    float inv = 1.f / fmaxf(s_run, 1e-8f);
    ((float4*)ns_out)[nd * 32 + lane] = make_float4(ax * inv, ay * inv,
                                                    az * inv, aw * inv);

    // sweep 2: normalize scores -> attn_out. 4 edges per iteration.
    const int h2 = lane & 7;
    const float m_h = __shfl_sync(0xffffffff, m_run, h2 << 2);
    const float i_h = __shfl_sync(0xffffffff, inv,   h2 << 2);
    for (int j0 = beg; j0 < end; j0 += 4) {
        int j = j0 + (lane >> 3);
        if (j < end) {
            int eid = g_edge[j].x;
            float sc = g_scores[(size_t)j * HH + h2];
            float a = (sc > -1e8f) ? __expf(sc - m_h) * i_h : 0.f;
            attn_out[(size_t)eid * HH + h2] = a;
        }
    }
}

// ---------------- launch ------------------------------------------------------
extern "C" void kernel_launch(void* const* d_in, const int* in_sizes, int n_in,
                              void* d_out, int out_size) {
    const float* x   = (const float*)d_in[0];
    const float* pi  = (const float*)d_in[1];
    const float* vw  = (const float*)d_in[2];
    const float* Wq  = (const float*)d_in[3];
    const float* bq  = (const float*)d_in[4];
    const float* Wk  = (const float*)d_in[5];
    const float* bk  = (const float*)d_in[6];
    const float* Wv  = (const float*)d_in[7];
    const float* bv  = (const float*)d_in[8];
    const int*   src = (const int*)d_in[9];
    const int*   dst = (const int*)d_in[10];

    const int n = in_sizes[0] / DD;   // 100000
    const int E = in_sizes[9];        // 1600000

    float* out = (float*)d_out;
    float* ns_out = out;                          // [n, H, DH]
    float* attn_out = out + (size_t)n * DD;       // [E, H]

    // One-time host resource init (no device memory involved).
    static cudaStream_t sB = nullptr;
    static cudaEvent_t eFork = nullptr, eJoin = nullptr;
    if (sB == nullptr) {
        cudaStreamCreateWithFlags(&sB, cudaStreamNonBlocking);
        cudaEventCreateWithFlags(&eFork, cudaEventDisableTiming);
        cudaEventCreateWithFlags(&eJoin, cudaEventDisableTiming);
        cudaFuncSetAttribute(qkv_gemm_tc,
                             cudaFuncAttributeMaxDynamicSharedMemorySize,
                             GEMM_SMEM);
    }

    const int nb = (n + 1023) / 1024;

    // Fork: CSR chain on side stream, GEMM on main stream (concurrent).
    cudaEventRecord(eFork, 0);
    cudaStreamWaitEvent(sB, eFork, 0);

    hist_kernel<<<(E + 255) / 256, 256, 0, sB>>>(dst, E);
    scan1<<<nb, 1024, 0, sB>>>(n);
    scan3<<<nb, 1024, 0, sB>>>(n, E);

    qkv_gemm_tc<<<(n + 127) / 128, 256, GEMM_SMEM>>>(x, Wq, bq, Wk, bk, Wv, bv, n);  // 4th: profiled

    scatter_kernel<<<(E + 255) / 256, 256, 0, sB>>>(src, dst, E);
    cudaEventRecord(eJoin, sB);

    // Join: node_attn needs both the GEMM outputs and the CSR edge list.
    cudaStreamWaitEvent(0, eJoin, 0);
    node_attn<<<(n + 7) / 8, 256>>>(pi, vw, ns_out, attn_out, n);
}